// round 1
// baseline (speedup 1.0000x reference)
#include <cuda_runtime.h>
#include <math.h>

typedef unsigned long long ull;

#define T_STEPS 64
#define BATCH   32
#define VOCAB   32000
#define EDIM    512
#define HDIM    512
#define G4      2048   // 4*H

// -------- scratch (static __device__, allocation-free) --------
__device__ float g_XP[(size_t)T_STEPS * BATCH * G4];  // 2048 x 2048 precomputed input projection (+biases)
__device__ float g_hbuf[2][BATCH * HDIM];             // double-buffered hidden state
__device__ float g_c[BATCH * HDIM];                   // cell state (element-owned per block, safe in place)
__device__ float g_htmp[BATCH * HDIM];                // tentative hidden (used by logits)

// -------- smem layout for the GEMM-ish kernels --------
#define SAT_STRIDE  36     // padded stride for A^T [512][36] floats (16B-aligned rows, low conflicts)
#define SOUT_STRIDE 136    // padded stride for out-transpose [32][136]
#define SMEM_FLOATS (512 * SAT_STRIDE + 32 * SOUT_STRIDE)
#define SMEM_BYTES  (SMEM_FLOATS * 4)

__device__ __forceinline__ ull pack2(float lo, float hi) {
    ull r;
    asm("mov.b64 %0, {%1, %2};" : "=l"(r) : "f"(lo), "f"(hi));
    return r;
}
__device__ __forceinline__ void unpack2(ull v, float& lo, float& hi) {
    unsigned a, b;
    asm("mov.b64 {%0, %1}, %2;" : "=r"(a), "=r"(b) : "l"(v));
    lo = __uint_as_float(a); hi = __uint_as_float(b);
}
__device__ __forceinline__ void ffma2(ull& acc, ull a, ull b) {
    asm("fma.rn.f32x2 %0, %1, %2, %0;" : "+l"(acc) : "l"(a), "l"(b));
}

// ================= init: h0,c0 -> scratch =================
__global__ void init_kernel(const float* __restrict__ h0, const float* __restrict__ c0) {
    int i = blockIdx.x * blockDim.x + threadIdx.x;
    if (i < BATCH * HDIM) {
        g_hbuf[0][i] = h0[i];
        g_c[i]       = c0[i];
    }
}

// ================= precompute: XP[i][g] = emb[tok[i]] . W_ih[g] + b_ih[g] + b_hh[g] =================
// grid: (G4/128, 2048/32) ; block: 256 threads ; block tile = 128 g-rows x 32 i-rows, K=512
__global__ void precompute_kernel(const int* __restrict__ tokens,
                                  const float* __restrict__ emb,
                                  const float* __restrict__ W_ih,
                                  const float* __restrict__ b_ih,
                                  const float* __restrict__ b_hh) {
    extern __shared__ float sm[];
    float* sA = sm;                       // A^T: [k][i_local], stride SAT_STRIDE
    float* sO = sm + 512 * SAT_STRIDE;    // out transpose: [i_local][g_local], stride SOUT_STRIDE

    int g0 = blockIdx.x * 128;
    int i0 = blockIdx.y * 32;
    int tid = threadIdx.x;

    // stage embeddings transposed
    for (int slot = tid; slot < 32 * 128; slot += 256) {
        int il = slot >> 7, q = slot & 127;
        int tok = tokens[i0 + il];
        float4 v = *(const float4*)(emb + (size_t)tok * EDIM + q * 4);
        sA[(4 * q + 0) * SAT_STRIDE + il] = v.x;
        sA[(4 * q + 1) * SAT_STRIDE + il] = v.y;
        sA[(4 * q + 2) * SAT_STRIDE + il] = v.z;
        sA[(4 * q + 3) * SAT_STRIDE + il] = v.w;
    }
    __syncthreads();

    int gl = tid >> 1;
    int b0 = (tid & 1) * 16;
    const float* wrow = W_ih + (size_t)(g0 + gl) * EDIM;

    ull acc[8];
#pragma unroll
    for (int m = 0; m < 8; m++) acc[m] = 0ull;

    float4 wv = *(const float4*)(wrow);
    for (int k = 0; k < 512; k += 4) {
        float4 wn = make_float4(0.f, 0.f, 0.f, 0.f);
        if (k + 4 < 512) wn = *(const float4*)(wrow + k + 4);
#pragma unroll
        for (int e = 0; e < 4; e++) {
            float w = (e == 0) ? wv.x : (e == 1) ? wv.y : (e == 2) ? wv.z : wv.w;
            ull w2 = pack2(w, w);
            const double2* hp = (const double2*)(sA + (size_t)(k + e) * SAT_STRIDE + b0);
#pragma unroll
            for (int m = 0; m < 4; m++) {
                double2 hv = hp[m];
                ffma2(acc[2 * m + 0], (ull)__double_as_longlong(hv.x), w2);
                ffma2(acc[2 * m + 1], (ull)__double_as_longlong(hv.y), w2);
            }
        }
        wv = wn;
    }

    float bias = b_ih[g0 + gl] + b_hh[g0 + gl];
#pragma unroll
    for (int m = 0; m < 8; m++) {
        float lo, hi; unpack2(acc[m], lo, hi);
        sO[(b0 + 2 * m + 0) * SOUT_STRIDE + gl] = lo + bias;
        sO[(b0 + 2 * m + 1) * SOUT_STRIDE + gl] = hi + bias;
    }
    __syncthreads();

    for (int slot = tid; slot < 1024; slot += 256) {
        int il = slot >> 5, gq = slot & 31;
        float4 v = *(const float4*)(sO + il * SOUT_STRIDE + gq * 4);
        *(float4*)(g_XP + (size_t)(i0 + il) * G4 + g0 + gq * 4) = v;
    }
}

// ================= recurrent step: gates = XP[t] + h @ W_hh^T ; LSTM pointwise ; update h,c,htmp =================
// grid: 128 blocks (4 j's each) ; block: 128 threads. Rows owned: {e*512 + jb + jj}, all 4 gates of a j in-block.
__global__ void recurrent_kernel(const float* __restrict__ W_hh,
                                 const int* __restrict__ tokens, int t) {
    __shared__ float s_g[16][33];
    int tid = threadIdx.x;
    int jb = blockIdx.x * 4;
    int r = tid & 15, bq = tid >> 4;      // r: local row 0..15, bq: batch group (4 b's)
    int e = r >> 2, jj = r & 3;
    int row = e * HDIM + jb + jj;

    const float* wrow = W_hh + (size_t)row * HDIM;
    const float* hold = g_hbuf[t & 1];

    // packed-over-k accumulators; init with XP in lane0
    ull acc[4];
#pragma unroll
    for (int m = 0; m < 4; m++) {
        float xp = g_XP[(size_t)(t * BATCH + bq * 4 + m) * G4 + row];
        acc[m] = pack2(xp, 0.0f);
    }

    for (int k = 0; k < 512; k += 4) {
        double2 wd = *(const double2*)(wrow + k);
        ull w2a = (ull)__double_as_longlong(wd.x);
        ull w2b = (ull)__double_as_longlong(wd.y);
#pragma unroll
        for (int m = 0; m < 4; m++) {
            double2 hd = *(const double2*)(hold + (size_t)(bq * 4 + m) * HDIM + k);
            ffma2(acc[m], (ull)__double_as_longlong(hd.x), w2a);
            ffma2(acc[m], (ull)__double_as_longlong(hd.y), w2b);
        }
    }

#pragma unroll
    for (int m = 0; m < 4; m++) {
        float lo, hi; unpack2(acc[m], lo, hi);
        s_g[r][bq * 4 + m] = lo + hi;
    }
    __syncthreads();

    // pointwise LSTM update: 128 threads = 32 b x 4 j
    int b = tid & 31, j2 = tid >> 5;
    float ig = s_g[0 + j2][b];
    float fg = s_g[4 + j2][b];
    float gg = s_g[8 + j2][b];
    float og = s_g[12 + j2][b];

    float iv = 1.0f / (1.0f + expf(-ig));
    float fv = 1.0f / (1.0f + expf(-fg));
    float gv = tanhf(gg);
    float ov = 1.0f / (1.0f + expf(-og));

    int j = jb + j2;
    int idx = b * HDIM + j;
    float cold = g_c[idx];
    float ctmp = fv * cold + iv * gv;
    float htmp = ov * tanhf(ctmp);
    bool msk = tokens[t * BATCH + b] != 0;   // PAD = 0

    g_htmp[idx] = htmp;                              // logits always use tentative hidden
    g_hbuf[(t + 1) & 1][idx] = msk ? htmp : hold[idx];
    g_c[idx] = msk ? ctmp : cold;
}

// ================= logits: out[t][b][v] = b_fc[v] + htmp[b] . W_fc[v] =================
// grid: 250 blocks (128 v each) ; block: 256 threads ; h staged transposed in smem
__global__ void logits_kernel(const float* __restrict__ W_fc,
                              const float* __restrict__ b_fc,
                              float* __restrict__ out, int t) {
    extern __shared__ float sm[];
    float* sA = sm;                       // htmp^T: [k][b], stride SAT_STRIDE
    float* sO = sm + 512 * SAT_STRIDE;    // out transpose: [b][v_local], stride SOUT_STRIDE

    int v0 = blockIdx.x * 128;
    int tid = threadIdx.x;

    for (int slot = tid; slot < 32 * 128; slot += 256) {
        int b = slot >> 7, q = slot & 127;
        float4 h4 = *(const float4*)(g_htmp + (size_t)b * HDIM + q * 4);
        sA[(4 * q + 0) * SAT_STRIDE + b] = h4.x;
        sA[(4 * q + 1) * SAT_STRIDE + b] = h4.y;
        sA[(4 * q + 2) * SAT_STRIDE + b] = h4.z;
        sA[(4 * q + 3) * SAT_STRIDE + b] = h4.w;
    }
    __syncthreads();

    int vl = tid >> 1;
    int b0 = (tid & 1) * 16;
    const float* wrow = W_fc + (size_t)(v0 + vl) * HDIM;

    ull acc[8];
#pragma unroll
    for (int m = 0; m < 8; m++) acc[m] = 0ull;

    float4 wv = *(const float4*)(wrow);
    for (int k = 0; k < 512; k += 4) {
        float4 wn = make_float4(0.f, 0.f, 0.f, 0.f);
        if (k + 4 < 512) wn = *(const float4*)(wrow + k + 4);
#pragma unroll
        for (int e = 0; e < 4; e++) {
            float w = (e == 0) ? wv.x : (e == 1) ? wv.y : (e == 2) ? wv.z : wv.w;
            ull w2 = pack2(w, w);
            const double2* hp = (const double2*)(sA + (size_t)(k + e) * SAT_STRIDE + b0);
#pragma unroll
            for (int m = 0; m < 4; m++) {
                double2 hv = hp[m];
                ffma2(acc[2 * m + 0], (ull)__double_as_longlong(hv.x), w2);
                ffma2(acc[2 * m + 1], (ull)__double_as_longlong(hv.y), w2);
            }
        }
        wv = wn;
    }

    float bias = b_fc[v0 + vl];
#pragma unroll
    for (int m = 0; m < 8; m++) {
        float lo, hi; unpack2(acc[m], lo, hi);
        sO[(b0 + 2 * m + 0) * SOUT_STRIDE + vl] = lo + bias;
        sO[(b0 + 2 * m + 1) * SOUT_STRIDE + vl] = hi + bias;
    }
    __syncthreads();

    float* obase = out + (size_t)t * BATCH * VOCAB;
    for (int slot = tid; slot < 1024; slot += 256) {
        int b = slot >> 5, vq = slot & 31;
        float4 v4 = *(const float4*)(sO + b * SOUT_STRIDE + vq * 4);
        // streaming store: keep W_fc resident in L2
        __stcs((float4*)(obase + (size_t)b * VOCAB + v0 + vq * 4), v4);
    }
}

// ================= launch =================
extern "C" void kernel_launch(void* const* d_in, const int* in_sizes, int n_in,
                              void* d_out, int out_size) {
    const int*   tokens = (const int*)d_in[0];
    const float* emb    = (const float*)d_in[1];
    const float* W_ih   = (const float*)d_in[2];
    const float* W_hh   = (const float*)d_in[3];
    const float* b_ih   = (const float*)d_in[4];
    const float* b_hh   = (const float*)d_in[5];
    const float* W_fc   = (const float*)d_in[6];
    const float* b_fc   = (const float*)d_in[7];
    const float* h0     = (const float*)d_in[8];
    const float* c0     = (const float*)d_in[9];
    float* out = (float*)d_out;

    cudaFuncSetAttribute(precompute_kernel, cudaFuncAttributeMaxDynamicSharedMemorySize, SMEM_BYTES);
    cudaFuncSetAttribute(logits_kernel,     cudaFuncAttributeMaxDynamicSharedMemorySize, SMEM_BYTES);

    init_kernel<<<64, 256>>>(h0, c0);
    precompute_kernel<<<dim3(G4 / 128, (T_STEPS * BATCH) / 32), 256, SMEM_BYTES>>>(
        tokens, emb, W_ih, b_ih, b_hh);

    for (int t = 0; t < T_STEPS; t++) {
        recurrent_kernel<<<128, 128>>>(W_hh, tokens, t);
        logits_kernel<<<VOCAB / 128, 256, SMEM_BYTES>>>(W_fc, b_fc, out, t);
    }
}

// round 3
// speedup vs baseline: 2.1953x; 2.1953x over previous
#include <cuda_runtime.h>
#include <math.h>
#include <stdint.h>

typedef unsigned long long ull;

#define T_STEPS 64
#define BATCH   32
#define VOCAB   32000
#define HDIM    512
#define G4      2048
#define MTOT    (T_STEPS * BATCH)   // 2048

// ---------------- scratch (static __device__, allocation-free) ----------------
__device__ float  g_XPt[(size_t)T_STEPS * G4 * BATCH];   // [t][g][b] input proj + biases
__device__ float4 g_hT4[2][128 * 32];                    // [k4][b] hidden, float4 over k
__device__ float  g_cT[HDIM * BATCH];                    // [j][b] cell state
__device__ float  g_H[(size_t)MTOT * HDIM];              // [i][k] tentative hidden (GEMM A)
__device__ float4 g_W4[HDIM * HDIM];                     // [j][k] -> (wi, wf, wg, wo)

// ---------------- helpers ----------------
__device__ __forceinline__ ull pack2(float lo, float hi) {
    ull r; asm("mov.b64 %0, {%1, %2};" : "=l"(r) : "f"(lo), "f"(hi)); return r;
}
__device__ __forceinline__ void unpack2(ull v, float& lo, float& hi) {
    unsigned a, b; asm("mov.b64 {%0, %1}, %2;" : "=r"(a), "=r"(b) : "l"(v));
    lo = __uint_as_float(a); hi = __uint_as_float(b);
}
__device__ __forceinline__ void ffma2(ull& acc, ull a, ull b) {
    asm("fma.rn.f32x2 %0, %1, %2, %0;" : "+l"(acc) : "l"(a), "l"(b));
}

// ================= FFMA2 GEMM: C[M x N] = A[M x 512] * B[N x 512]^T (+bias) =================
// CTA tile 128m x 128v, 256 threads, per-thread 8m x 8v.
// MODE 0: logits  (A = g_H rows, bias0 = b_fc, writes out[i][v])
// MODE 1: precomp (A = emb[tokens[i]], bias0+bias1, writes g_XPt[t][g][b])
#define KC 16

template <int MODE>
__global__ void __launch_bounds__(256, 2)
gemm_kernel(const float* __restrict__ Bsrc,
            const float* __restrict__ bias0,
            const float* __restrict__ bias1,
            const int*   __restrict__ tokens,
            const float* __restrict__ emb,
            float* __restrict__ out) {
    // smem as pair-layout double arrays, row stride 65 doubles (130 floats) to spread banks
    __shared__ double sA2[KC * 65];
    __shared__ double sB2[KC * 65];
    float* fA = (float*)sA2;
    float* fB = (float*)sB2;

    int tid = threadIdx.x;
    int i0 = blockIdx.x * 128;
    int v0 = blockIdx.y * 128;
    int tm = tid & 15;     // m-group: rows tm*8 .. tm*8+7
    int tv = tid >> 4;     // v-group: cols tv*8 .. tv*8+7

    // ---- loader mapping: slot = m*4 + k4 ; thread owns slots tid and tid+256
    int mA1 = tid >> 2, k4 = tid & 3;
    int mA2 = mA1 + 64;
    int krow0 = k4 * 4;

    const float* pA1;
    const float* pA2;
    if (MODE == 0) {
        pA1 = g_H + (size_t)(i0 + mA1) * 512 + k4 * 4;
        pA2 = g_H + (size_t)(i0 + mA2) * 512 + k4 * 4;
    } else {
        int t1 = tokens[i0 + mA1], t2 = tokens[i0 + mA2];
        pA1 = emb + (size_t)t1 * 512 + k4 * 4;
        pA2 = emb + (size_t)t2 * 512 + k4 * 4;
    }
    const float* pB1 = Bsrc + (size_t)(v0 + mA1) * 512 + k4 * 4;
    const float* pB2 = Bsrc + (size_t)(v0 + mA2) * 512 + k4 * 4;

    // smem store bases (float index): A pair-layout, B plain
    int baseA1 = ((mA1 >> 1) & 3) * 32 + (mA1 >> 3) * 2 + (mA1 & 1);
    int baseA2 = ((mA2 >> 1) & 3) * 32 + (mA2 >> 3) * 2 + (mA2 & 1);
    int baseB1 = mA1, baseB2 = mA2;

    ull acc[4][8];
#pragma unroll
    for (int p = 0; p < 4; p++)
#pragma unroll
        for (int v = 0; v < 8; v++) acc[p][v] = pack2(0.0f, 0.0f);

    float4 ra1 = *(const float4*)pA1;
    float4 ra2 = *(const float4*)pA2;
    float4 rb1 = *(const float4*)pB1;
    float4 rb2 = *(const float4*)pB2;

    for (int c = 0; c < 32; c++) {
        __syncthreads();
        // store current chunk to smem (transposing into pair layout)
        fA[(krow0 + 0) * 130 + baseA1] = ra1.x;
        fA[(krow0 + 1) * 130 + baseA1] = ra1.y;
        fA[(krow0 + 2) * 130 + baseA1] = ra1.z;
        fA[(krow0 + 3) * 130 + baseA1] = ra1.w;
        fA[(krow0 + 0) * 130 + baseA2] = ra2.x;
        fA[(krow0 + 1) * 130 + baseA2] = ra2.y;
        fA[(krow0 + 2) * 130 + baseA2] = ra2.z;
        fA[(krow0 + 3) * 130 + baseA2] = ra2.w;
        fB[(krow0 + 0) * 130 + baseB1] = rb1.x;
        fB[(krow0 + 1) * 130 + baseB1] = rb1.y;
        fB[(krow0 + 2) * 130 + baseB1] = rb1.z;
        fB[(krow0 + 3) * 130 + baseB1] = rb1.w;
        fB[(krow0 + 0) * 130 + baseB2] = rb2.x;
        fB[(krow0 + 1) * 130 + baseB2] = rb2.y;
        fB[(krow0 + 2) * 130 + baseB2] = rb2.z;
        fB[(krow0 + 3) * 130 + baseB2] = rb2.w;
        __syncthreads();

        if (c < 31) {
            int off = (c + 1) * KC;
            ra1 = *(const float4*)(pA1 + off);
            ra2 = *(const float4*)(pA2 + off);
            rb1 = *(const float4*)(pB1 + off);
            rb2 = *(const float4*)(pB2 + off);
        }

#pragma unroll
        for (int k = 0; k < KC; k++) {
            ull a[4];
#pragma unroll
            for (int p = 0; p < 4; p++)
                a[p] = (ull)__double_as_longlong(sA2[k * 65 + p * 16 + tm]);
            ull bd[8];
#pragma unroll
            for (int q = 0; q < 4; q++) {
                ull bp = (ull)__double_as_longlong(sB2[k * 65 + tv * 4 + q]);
                float bl, bh; unpack2(bp, bl, bh);
                bd[2 * q + 0] = pack2(bl, bl);
                bd[2 * q + 1] = pack2(bh, bh);
            }
#pragma unroll
            for (int p = 0; p < 4; p++)
#pragma unroll
                for (int v = 0; v < 8; v++)
                    ffma2(acc[p][v], a[p], bd[v]);
        }
    }

    // ---------------- epilogue ----------------
    if (MODE == 0) {
        int vb = v0 + tv * 8;
        float4 bb0 = *(const float4*)(bias0 + vb);
        float4 bb1 = *(const float4*)(bias0 + vb + 4);
#pragma unroll
        for (int p = 0; p < 4; p++) {
            float rl[8], rh[8];
#pragma unroll
            for (int v = 0; v < 8; v++) unpack2(acc[p][v], rl[v], rh[v]);
            size_t r0 = (size_t)(i0 + tm * 8 + 2 * p) * VOCAB + vb;
            __stcs((float4*)(out + r0),
                   make_float4(rl[0] + bb0.x, rl[1] + bb0.y, rl[2] + bb0.z, rl[3] + bb0.w));
            __stcs((float4*)(out + r0 + 4),
                   make_float4(rl[4] + bb1.x, rl[5] + bb1.y, rl[6] + bb1.z, rl[7] + bb1.w));
            size_t r1 = r0 + VOCAB;
            __stcs((float4*)(out + r1),
                   make_float4(rh[0] + bb0.x, rh[1] + bb0.y, rh[2] + bb0.z, rh[3] + bb0.w));
            __stcs((float4*)(out + r1 + 4),
                   make_float4(rh[4] + bb1.x, rh[5] + bb1.y, rh[6] + bb1.z, rh[7] + bb1.w));
        }
    } else {
        int vb = v0 + tv * 8;
        float bias[8];
#pragma unroll
        for (int v = 0; v < 8; v++) bias[v] = bias0[vb + v] + bias1[vb + v];
#pragma unroll
        for (int p = 0; p < 4; p++) {
            int ilo = i0 + tm * 8 + 2 * p;
            int ihi = ilo + 1;
            size_t blo = (size_t)(ilo >> 5) * (G4 * BATCH) + (ilo & 31);
            size_t bhi = (size_t)(ihi >> 5) * (G4 * BATCH) + (ihi & 31);
#pragma unroll
            for (int v = 0; v < 8; v++) {
                float rl, rh; unpack2(acc[p][v], rl, rh);
                size_t goff = (size_t)(vb + v) * 32;
                g_XPt[blo + goff] = rl + bias[v];
                g_XPt[bhi + goff] = rh + bias[v];
            }
        }
    }
}

// ================= one-time W_hh transpose: g_W4[j][k] = (wi, wf, wg, wo) =================
__global__ void prep_W4(const float* __restrict__ W_hh) {
    int idx = blockIdx.x * 256 + threadIdx.x;   // 512*512 total
    int j = idx >> 9, k = idx & 511;
    g_W4[(size_t)j * 512 + k] = make_float4(
        W_hh[(size_t)(0 * 512 + j) * 512 + k],
        W_hh[(size_t)(1 * 512 + j) * 512 + k],
        W_hh[(size_t)(2 * 512 + j) * 512 + k],
        W_hh[(size_t)(3 * 512 + j) * 512 + k]);
}

// ================= init: h0,c0 -> transposed scratch =================
__global__ void init_kernel(const float* __restrict__ h0, const float* __restrict__ c0) {
    int idx = blockIdx.x * blockDim.x + threadIdx.x;
    if (idx < BATCH * HDIM) {
        int j = idx >> 5, b = idx & 31;
        ((float*)g_hT4[0])[(j >> 2) * 128 + b * 4 + (j & 3)] = h0[b * HDIM + j];
        g_cT[j * 32 + b] = c0[b * HDIM + j];
    }
}

// ================= recurrent step (register-resident, gate-paired weights) =================
__global__ void __launch_bounds__(128, 8)
recurrent_kernel(const int* __restrict__ tokens, int t) {
    int tid = threadIdx.x;
    int w = tid >> 5, b = tid & 31;
    int j = blockIdx.x * 4 + w;

    const float4*  hT = g_hT4[t & 1];
    const double2* wp = (const double2*)(g_W4 + (size_t)j * 512);

    size_t xb = (size_t)t * (G4 * BATCH) + (size_t)b;
    ull aif[2], ago[2];
    aif[0] = pack2(g_XPt[xb + (size_t)(0 * 512 + j) * 32],
                   g_XPt[xb + (size_t)(1 * 512 + j) * 32]);
    ago[0] = pack2(g_XPt[xb + (size_t)(2 * 512 + j) * 32],
                   g_XPt[xb + (size_t)(3 * 512 + j) * 32]);
    aif[1] = pack2(0.0f, 0.0f);
    ago[1] = pack2(0.0f, 0.0f);

#pragma unroll 4
    for (int k4 = 0; k4 < 128; k4++) {
        float4  h4 = hT[k4 * 32 + b];
        double2 w0 = wp[k4 * 4 + 0];
        double2 w1 = wp[k4 * 4 + 1];
        double2 w2 = wp[k4 * 4 + 2];
        double2 w3 = wp[k4 * 4 + 3];
        ull hx = pack2(h4.x, h4.x), hy = pack2(h4.y, h4.y);
        ull hz = pack2(h4.z, h4.z), hw = pack2(h4.w, h4.w);
        ffma2(aif[0], hx, (ull)__double_as_longlong(w0.x));
        ffma2(ago[0], hx, (ull)__double_as_longlong(w0.y));
        ffma2(aif[1], hy, (ull)__double_as_longlong(w1.x));
        ffma2(ago[1], hy, (ull)__double_as_longlong(w1.y));
        ffma2(aif[0], hz, (ull)__double_as_longlong(w2.x));
        ffma2(ago[0], hz, (ull)__double_as_longlong(w2.y));
        ffma2(aif[1], hw, (ull)__double_as_longlong(w3.x));
        ffma2(ago[1], hw, (ull)__double_as_longlong(w3.y));
    }

    float i0a, f0a, i0b, f0b, g0a, o0a, g0b, o0b;
    unpack2(aif[0], i0a, f0a); unpack2(aif[1], i0b, f0b);
    unpack2(ago[0], g0a, o0a); unpack2(ago[1], g0b, o0b);
    float ig = i0a + i0b, fg = f0a + f0b, gg = g0a + g0b, og = o0a + o0b;

    float iv = 1.0f / (1.0f + expf(-ig));
    float fv = 1.0f / (1.0f + expf(-fg));
    float gv = tanhf(gg);
    float ov = 1.0f / (1.0f + expf(-og));

    float cold = g_cT[j * 32 + b];
    float ctmp = fv * cold + iv * gv;
    float htmp = ov * tanhf(ctmp);
    bool  msk  = tokens[t * BATCH + b] != 0;   // PAD = 0

    g_H[((size_t)t * BATCH + b) * HDIM + j] = htmp;
    float hold = ((const float*)hT)[(j >> 2) * 128 + b * 4 + (j & 3)];
    ((float*)g_hT4[(t + 1) & 1])[(j >> 2) * 128 + b * 4 + (j & 3)] = msk ? htmp : hold;
    g_cT[j * 32 + b] = msk ? ctmp : cold;
}

// ================= launch =================
extern "C" void kernel_launch(void* const* d_in, const int* in_sizes, int n_in,
                              void* d_out, int out_size) {
    const int*   tokens = (const int*)d_in[0];
    const float* emb    = (const float*)d_in[1];
    const float* W_ih   = (const float*)d_in[2];
    const float* W_hh   = (const float*)d_in[3];
    const float* b_ih   = (const float*)d_in[4];
    const float* b_hh   = (const float*)d_in[5];
    const float* W_fc   = (const float*)d_in[6];
    const float* b_fc   = (const float*)d_in[7];
    const float* h0     = (const float*)d_in[8];
    const float* c0     = (const float*)d_in[9];
    float* out = (float*)d_out;

    init_kernel<<<64, 256>>>(h0, c0);
    prep_W4<<<1024, 256>>>(W_hh);

    // XPt = emb[tok] @ W_ih^T + (b_ih + b_hh):  M=2048, N=2048, K=512
    gemm_kernel<1><<<dim3(16, 16), 256>>>(W_ih, b_ih, b_hh, tokens, emb, nullptr);

    for (int t = 0; t < T_STEPS; t++)
        recurrent_kernel<<<128, 128>>>(tokens, t);

    // out = H @ W_fc^T + b_fc:  M=2048, N=32000, K=512
    gemm_kernel<0><<<dim3(16, 250), 256>>>(W_fc, b_fc, nullptr, nullptr, nullptr, out);
}

// round 4
// speedup vs baseline: 2.6770x; 1.2194x over previous
#include <cuda_runtime.h>
#include <math.h>
#include <stdint.h>

typedef unsigned long long ull;

#define T_STEPS 64
#define BATCH   32
#define VOCAB   32000
#define HDIM    512
#define G4      2048
#define MTOT    (T_STEPS * BATCH)   // 2048

// ---------------- scratch (static __device__, allocation-free) ----------------
__device__ float  g_XPt[(size_t)T_STEPS * G4 * BATCH];   // [t][g][b] input proj + biases
__device__ float4 g_hT4[2][128 * 32];                    // [k4][b] hidden, float4 over k
__device__ float  g_cT[HDIM * BATCH];                    // [j][b] cell state
__device__ float  g_H[(size_t)MTOT * HDIM];              // [i][k] tentative hidden (GEMM A)
__device__ float4 g_W4[HDIM * HDIM];                     // [j][k] -> (wi, wf, wg, wo)

// ---------------- helpers ----------------
__device__ __forceinline__ ull pack2(float lo, float hi) {
    ull r; asm("mov.b64 %0, {%1, %2};" : "=l"(r) : "f"(lo), "f"(hi)); return r;
}
__device__ __forceinline__ void unpack2(ull v, float& lo, float& hi) {
    unsigned a, b; asm("mov.b64 {%0, %1}, %2;" : "=r"(a), "=r"(b) : "l"(v));
    lo = __uint_as_float(a); hi = __uint_as_float(b);
}
__device__ __forceinline__ void ffma2(ull& acc, ull a, ull b) {
    asm("fma.rn.f32x2 %0, %1, %2, %0;" : "+l"(acc) : "l"(a), "l"(b));
}
__device__ __forceinline__ ull d2u(double d) { return (ull)__double_as_longlong(d); }

// ================= FFMA2 GEMM: C[M x N] = A[M x 512] * B[N x 512]^T (+bias) =================
// CTA tile 128m x 128v, 256 threads, per-thread 8m x 8v.
// MODE 0: logits  (A = g_H rows, bias0 = b_fc, writes out[i][v])
// MODE 1: precomp (A = emb[tokens[i]], bias0+bias1, writes g_XPt[t][g][b])
#define KC 16

template <int MODE>
__global__ void __launch_bounds__(256, 2)
gemm_kernel(const float* __restrict__ Bsrc,
            const float* __restrict__ bias0,
            const float* __restrict__ bias1,
            const int*   __restrict__ tokens,
            const float* __restrict__ emb,
            float* __restrict__ out) {
    // A: pair layout (65 ull per k-row). B: duplicated pairs (v,v), 130 ull per k-row.
    __shared__ ull sAu[KC * 65];
    __shared__ ull sBu[KC * 130];
    float* fA = (float*)sAu;

    int tid = threadIdx.x;
    int i0 = blockIdx.x * 128;
    int v0 = blockIdx.y * 128;
    int tm = tid & 15;     // m-group: rows tm*8 .. tm*8+7
    int tv = tid >> 4;     // v-group: cols tv*8 .. tv*8+7

    // ---- loader mapping
    int mA1 = tid >> 2, k4 = tid & 3;
    int mA2 = mA1 + 64;
    int krow0 = k4 * 4;

    const float* pA1;
    const float* pA2;
    if (MODE == 0) {
        pA1 = g_H + (size_t)(i0 + mA1) * 512 + k4 * 4;
        pA2 = g_H + (size_t)(i0 + mA2) * 512 + k4 * 4;
    } else {
        int t1 = tokens[i0 + mA1], t2 = tokens[i0 + mA2];
        pA1 = emb + (size_t)t1 * 512 + k4 * 4;
        pA2 = emb + (size_t)t2 * 512 + k4 * 4;
    }
    const float* pB1 = Bsrc + (size_t)(v0 + mA1) * 512 + k4 * 4;
    const float* pB2 = Bsrc + (size_t)(v0 + mA2) * 512 + k4 * 4;

    // A pair-layout float-index base within a 130-float k-row
    int baseA1 = ((mA1 >> 1) & 3) * 32 + (mA1 >> 3) * 2 + (mA1 & 1);
    int baseA2 = ((mA2 >> 1) & 3) * 32 + (mA2 >> 3) * 2 + (mA2 & 1);

    ull acc[4][8];
#pragma unroll
    for (int p = 0; p < 4; p++)
#pragma unroll
        for (int v = 0; v < 8; v++) acc[p][v] = pack2(0.0f, 0.0f);

    float4 ra1 = *(const float4*)pA1;
    float4 ra2 = *(const float4*)pA2;
    float4 rb1 = *(const float4*)pB1;
    float4 rb2 = *(const float4*)pB2;

    for (int c = 0; c < 32; c++) {
        __syncthreads();
        // A: transpose into pair layout (float stores)
        fA[(krow0 + 0) * 130 + baseA1] = ra1.x;
        fA[(krow0 + 1) * 130 + baseA1] = ra1.y;
        fA[(krow0 + 2) * 130 + baseA1] = ra1.z;
        fA[(krow0 + 3) * 130 + baseA1] = ra1.w;
        fA[(krow0 + 0) * 130 + baseA2] = ra2.x;
        fA[(krow0 + 1) * 130 + baseA2] = ra2.y;
        fA[(krow0 + 2) * 130 + baseA2] = ra2.z;
        fA[(krow0 + 3) * 130 + baseA2] = ra2.w;
        // B: duplicated pair stores (ull)
        sBu[(krow0 + 0) * 130 + mA1] = pack2(rb1.x, rb1.x);
        sBu[(krow0 + 1) * 130 + mA1] = pack2(rb1.y, rb1.y);
        sBu[(krow0 + 2) * 130 + mA1] = pack2(rb1.z, rb1.z);
        sBu[(krow0 + 3) * 130 + mA1] = pack2(rb1.w, rb1.w);
        sBu[(krow0 + 0) * 130 + mA2] = pack2(rb2.x, rb2.x);
        sBu[(krow0 + 1) * 130 + mA2] = pack2(rb2.y, rb2.y);
        sBu[(krow0 + 2) * 130 + mA2] = pack2(rb2.z, rb2.z);
        sBu[(krow0 + 3) * 130 + mA2] = pack2(rb2.w, rb2.w);
        __syncthreads();

        if (c < 31) {
            int off = (c + 1) * KC;
            ra1 = *(const float4*)(pA1 + off);
            ra2 = *(const float4*)(pA2 + off);
            rb1 = *(const float4*)(pB1 + off);
            rb2 = *(const float4*)(pB2 + off);
        }

#pragma unroll
        for (int k = 0; k < KC; k++) {
            ull a[4];
#pragma unroll
            for (int p = 0; p < 4; p++)
                a[p] = sAu[k * 65 + p * 16 + tm];
            ull bd[8];
#pragma unroll
            for (int v = 0; v < 8; v++)
                bd[v] = sBu[k * 130 + tv * 8 + v];
#pragma unroll
            for (int p = 0; p < 4; p++)
#pragma unroll
                for (int v = 0; v < 8; v++)
                    ffma2(acc[p][v], a[p], bd[v]);
        }
    }

    // ---------------- epilogue ----------------
    if (MODE == 0) {
        int vb = v0 + tv * 8;
        float4 bb0 = *(const float4*)(bias0 + vb);
        float4 bb1 = *(const float4*)(bias0 + vb + 4);
#pragma unroll
        for (int p = 0; p < 4; p++) {
            float rl[8], rh[8];
#pragma unroll
            for (int v = 0; v < 8; v++) unpack2(acc[p][v], rl[v], rh[v]);
            size_t r0 = (size_t)(i0 + tm * 8 + 2 * p) * VOCAB + vb;
            __stcs((float4*)(out + r0),
                   make_float4(rl[0] + bb0.x, rl[1] + bb0.y, rl[2] + bb0.z, rl[3] + bb0.w));
            __stcs((float4*)(out + r0 + 4),
                   make_float4(rl[4] + bb1.x, rl[5] + bb1.y, rl[6] + bb1.z, rl[7] + bb1.w));
            size_t r1 = r0 + VOCAB;
            __stcs((float4*)(out + r1),
                   make_float4(rh[0] + bb0.x, rh[1] + bb0.y, rh[2] + bb0.z, rh[3] + bb0.w));
            __stcs((float4*)(out + r1 + 4),
                   make_float4(rh[4] + bb1.x, rh[5] + bb1.y, rh[6] + bb1.z, rh[7] + bb1.w));
        }
    } else {
        int vb = v0 + tv * 8;
        float bias[8];
#pragma unroll
        for (int v = 0; v < 8; v++) bias[v] = bias0[vb + v] + bias1[vb + v];
#pragma unroll
        for (int p = 0; p < 4; p++) {
            int ilo = i0 + tm * 8 + 2 * p;
            int ihi = ilo + 1;
            size_t blo = (size_t)(ilo >> 5) * (G4 * BATCH) + (ilo & 31);
            size_t bhi = (size_t)(ihi >> 5) * (G4 * BATCH) + (ihi & 31);
#pragma unroll
            for (int v = 0; v < 8; v++) {
                float rl, rh; unpack2(acc[p][v], rl, rh);
                size_t goff = (size_t)(vb + v) * 32;
                g_XPt[blo + goff] = rl + bias[v];
                g_XPt[bhi + goff] = rh + bias[v];
            }
        }
    }
}

// ================= one-time W_hh transpose: g_W4[j][k] = (wi, wf, wg, wo) =================
__global__ void prep_W4(const float* __restrict__ W_hh) {
    int idx = blockIdx.x * 256 + threadIdx.x;   // 512*512 total
    int j = idx >> 9, k = idx & 511;
    g_W4[(size_t)j * 512 + k] = make_float4(
        W_hh[(size_t)(0 * 512 + j) * 512 + k],
        W_hh[(size_t)(1 * 512 + j) * 512 + k],
        W_hh[(size_t)(2 * 512 + j) * 512 + k],
        W_hh[(size_t)(3 * 512 + j) * 512 + k]);
}

// ================= init: h0,c0 -> transposed scratch =================
__global__ void init_kernel(const float* __restrict__ h0, const float* __restrict__ c0) {
    int idx = blockIdx.x * blockDim.x + threadIdx.x;
    if (idx < BATCH * HDIM) {
        int j = idx >> 5, b = idx & 31;
        ((float*)g_hT4[0])[(j >> 2) * 128 + b * 4 + (j & 3)] = h0[b * HDIM + j];
        g_cT[j * 32 + b] = c0[b * HDIM + j];
    }
}

// ================= recurrent step: K-split x4, CTA = one j =================
// grid 512 CTAs x 128 threads. warp w: k in [w*128, w*128+128), lane = b.
__global__ void __launch_bounds__(128, 4)
recurrent_kernel(const int* __restrict__ tokens, int t) {
    __shared__ float4 sred[4][32];
    int tid = threadIdx.x;
    int w = tid >> 5, b = tid & 31;
    int j = blockIdx.x;

    const float4*  hT = g_hT4[t & 1];
    const double2* wp = (const double2*)(g_W4 + (size_t)j * 512) + (size_t)w * 128;
    const float4*  hp = hT + w * 32 * 32;

    ull aif0 = pack2(0.0f, 0.0f), aif1 = pack2(0.0f, 0.0f);
    ull ago0 = pack2(0.0f, 0.0f), ago1 = pack2(0.0f, 0.0f);

#pragma unroll 8
    for (int kk = 0; kk < 32; kk++) {
        float4  h4 = hp[kk * 32 + b];
        double2 w0 = wp[kk * 4 + 0];
        double2 w1 = wp[kk * 4 + 1];
        double2 w2 = wp[kk * 4 + 2];
        double2 w3 = wp[kk * 4 + 3];
        ull hx = pack2(h4.x, h4.x), hy = pack2(h4.y, h4.y);
        ull hz = pack2(h4.z, h4.z), hw = pack2(h4.w, h4.w);
        ffma2(aif0, hx, d2u(w0.x));
        ffma2(ago0, hx, d2u(w0.y));
        ffma2(aif1, hy, d2u(w1.x));
        ffma2(ago1, hy, d2u(w1.y));
        ffma2(aif0, hz, d2u(w2.x));
        ffma2(ago0, hz, d2u(w2.y));
        ffma2(aif1, hw, d2u(w3.x));
        ffma2(ago1, hw, d2u(w3.y));
    }

    float ia, fa, ib, fb, ga, oa, gb, ob;
    unpack2(aif0, ia, fa); unpack2(aif1, ib, fb);
    unpack2(ago0, ga, oa); unpack2(ago1, gb, ob);
    sred[w][b] = make_float4(ia + ib, fa + fb, ga + gb, oa + ob);
    __syncthreads();

    if (w == 0) {
        float4 s0 = sred[0][b], s1 = sred[1][b], s2 = sred[2][b], s3 = sred[3][b];
        size_t xb = (size_t)t * (G4 * BATCH) + (size_t)b;
        float ig = s0.x + s1.x + s2.x + s3.x + g_XPt[xb + (size_t)(0 * 512 + j) * 32];
        float fg = s0.y + s1.y + s2.y + s3.y + g_XPt[xb + (size_t)(1 * 512 + j) * 32];
        float gg = s0.z + s1.z + s2.z + s3.z + g_XPt[xb + (size_t)(2 * 512 + j) * 32];
        float og = s0.w + s1.w + s2.w + s3.w + g_XPt[xb + (size_t)(3 * 512 + j) * 32];

        float iv = 1.0f / (1.0f + expf(-ig));
        float fv = 1.0f / (1.0f + expf(-fg));
        float gv = tanhf(gg);
        float ov = 1.0f / (1.0f + expf(-og));

        float cold = g_cT[j * 32 + b];
        float ctmp = fv * cold + iv * gv;
        float htmp = ov * tanhf(ctmp);
        bool  msk  = tokens[t * BATCH + b] != 0;   // PAD = 0

        g_H[((size_t)t * BATCH + b) * HDIM + j] = htmp;
        float hold = ((const float*)hT)[(j >> 2) * 128 + b * 4 + (j & 3)];
        ((float*)g_hT4[(t + 1) & 1])[(j >> 2) * 128 + b * 4 + (j & 3)] = msk ? htmp : hold;
        g_cT[j * 32 + b] = msk ? ctmp : cold;
    }
}

// ================= launch =================
extern "C" void kernel_launch(void* const* d_in, const int* in_sizes, int n_in,
                              void* d_out, int out_size) {
    const int*   tokens = (const int*)d_in[0];
    const float* emb    = (const float*)d_in[1];
    const float* W_ih   = (const float*)d_in[2];
    const float* W_hh   = (const float*)d_in[3];
    const float* b_ih   = (const float*)d_in[4];
    const float* b_hh   = (const float*)d_in[5];
    const float* W_fc   = (const float*)d_in[6];
    const float* b_fc   = (const float*)d_in[7];
    const float* h0     = (const float*)d_in[8];
    const float* c0     = (const float*)d_in[9];
    float* out = (float*)d_out;

    init_kernel<<<64, 256>>>(h0, c0);
    prep_W4<<<1024, 256>>>(W_hh);

    // XPt = emb[tok] @ W_ih^T + (b_ih + b_hh):  M=2048, N=2048, K=512
    gemm_kernel<1><<<dim3(16, 16), 256>>>(W_ih, b_ih, b_hh, tokens, emb, nullptr);

    for (int t = 0; t < T_STEPS; t++)
        recurrent_kernel<<<512, 128>>>(tokens, t);

    // out = H @ W_fc^T + b_fc:  M=2048, N=32000, K=512
    gemm_kernel<0><<<dim3(16, 250), 256>>>(W_fc, b_fc, nullptr, nullptr, nullptr, out);
}

// round 6
// speedup vs baseline: 3.9931x; 1.4916x over previous
#include <cuda_runtime.h>
#include <cuda_bf16.h>
#include <math.h>
#include <stdint.h>

typedef unsigned long long ull;

#define T_STEPS 64
#define BATCH   32
#define VOCAB   32000
#define HDIM    512
#define G4      2048
#define MTOT    (T_STEPS * BATCH)   // 2048
#define KX      1536                // 3 * HDIM (bf16x3 folded K)

// ---------------- scratch (static __device__, allocation-free) ----------------
__device__ float  g_XPt[(size_t)T_STEPS * G4 * BATCH];     // [t][g][b] input proj + biases
__device__ float4 g_hT4[2][128 * 32];                      // [k4][b] hidden, float4 over k
__device__ float  g_cT[HDIM * BATCH];                      // [j][b] cell state
__device__ float  g_H[(size_t)MTOT * HDIM];                // [i][k] tentative hidden
__device__ float4 g_W4[HDIM * HDIM];                       // [j][k] -> (wi, wf, wg, wo)
__device__ __align__(16) __nv_bfloat16 g_HX[(size_t)MTOT * KX];   // [i][hi|hi|lo]
__device__ __align__(16) __nv_bfloat16 g_WX[(size_t)VOCAB * KX];  // [v][hi|lo|hi]

// ---------------- helpers ----------------
__device__ __forceinline__ ull pack2(float lo, float hi) {
    ull r; asm("mov.b64 %0, {%1, %2};" : "=l"(r) : "f"(lo), "f"(hi)); return r;
}
__device__ __forceinline__ void unpack2(ull v, float& lo, float& hi) {
    unsigned a, b; asm("mov.b64 {%0, %1}, %2;" : "=r"(a), "=r"(b) : "l"(v));
    lo = __uint_as_float(a); hi = __uint_as_float(b);
}
__device__ __forceinline__ void ffma2(ull& acc, ull a, ull b) {
    asm("fma.rn.f32x2 %0, %1, %2, %0;" : "+l"(acc) : "l"(a), "l"(b));
}
__device__ __forceinline__ ull d2u(double d) { return (ull)__double_as_longlong(d); }
__device__ __forceinline__ uint32_t smem_u32(const void* p) {
    uint32_t a;
    asm("{ .reg .u64 t; cvta.to.shared.u64 t, %1; cvt.u32.u64 %0, t; }" : "=r"(a) : "l"(p));
    return a;
}
__device__ __forceinline__ void cp16(uint32_t saddr, const void* gaddr) {
    asm volatile("cp.async.cg.shared.global [%0], [%1], 16;" :: "r"(saddr), "l"(gaddr));
}
__device__ __forceinline__ uint4 ldsm_x4(uint32_t addr) {
    uint4 r;
    asm volatile("ldmatrix.sync.aligned.m8n8.x4.shared.b16 {%0,%1,%2,%3}, [%4];"
                 : "=r"(r.x), "=r"(r.y), "=r"(r.z), "=r"(r.w) : "r"(addr));
    return r;
}
__device__ __forceinline__ void mma16816(float* c, uint4 a, uint32_t b0, uint32_t b1) {
    asm volatile(
        "mma.sync.aligned.m16n8k16.row.col.f32.bf16.bf16.f32 "
        "{%0,%1,%2,%3}, {%4,%5,%6,%7}, {%8,%9}, {%0,%1,%2,%3};"
        : "+f"(c[0]), "+f"(c[1]), "+f"(c[2]), "+f"(c[3])
        : "r"(a.x), "r"(a.y), "r"(a.z), "r"(a.w), "r"(b0), "r"(b1));
}

// ================= HMMA logits GEMM: out[i][v] = HX[i] . WX[v] + b_fc[v] =================
// CTA 128m x 128n, 8 warps (2m x 4n), warp tile 64x32. K stages of 64 (24 stages).
// smem stage: A 4 planes of [128 rows x 32B] + B 4 planes; rows rotated by +plane (mod 128).
#define STAGE_B 32768
#define NSTAGE_LOGITS 24

__global__ void __launch_bounds__(256, 2)
logits_mma(const float* __restrict__ b_fc, float* __restrict__ out) {
    extern __shared__ char sm[];
    uint32_t smb = smem_u32(sm);
    int tid = threadIdx.x, wid = tid >> 5, lane = tid & 31;
    int i0 = blockIdx.x * 128;
    int v0 = blockIdx.y * 128;
    int m0w = (wid & 1) * 64;        // warp m offset within CTA tile
    int n0w = (wid >> 1) * 32;       // warp n offset

    // loader mapping: 256 threads x (4 A-chunks + 4 B-chunks) of 16B per stage
    int lrow = tid >> 3, lseg = tid & 7;
    int lplane = lseg >> 1, lhalf = lseg & 1;
    const __nv_bfloat16* gA = g_HX + (size_t)(i0 + lrow) * KX + lseg * 8;
    const __nv_bfloat16* gB = g_WX + (size_t)(v0 + lrow) * KX + lseg * 8;

    auto issue_stage = [&](int s) {
        uint32_t sb = (uint32_t)((s & 1) * STAGE_B);
        size_t gk = (size_t)s * 64;
#pragma unroll
        for (int i = 0; i < 4; i++) {
            // rotated row computed per chunk, wrap INSIDE the plane (bug fix)
            uint32_t ro = (uint32_t)(((lrow + i * 32 + lplane) & 127) * 32)
                        + (uint32_t)(lplane * 4096 + lhalf * 16);
            cp16(smb + sb + ro,          gA + gk + (size_t)i * 32 * KX);
            cp16(smb + sb + 16384 + ro,  gB + gk + (size_t)i * 32 * KX);
        }
        asm volatile("cp.async.commit_group;");
    };

    float acc[4][4][4];
#pragma unroll
    for (int a = 0; a < 4; a++)
#pragma unroll
        for (int b = 0; b < 4; b++)
#pragma unroll
            for (int r = 0; r < 4; r++) acc[a][b][r] = 0.0f;

    issue_stage(0);
    issue_stage(1);

    for (int s = 0; s < NSTAGE_LOGITS; s++) {
        asm volatile("cp.async.wait_group 1;");
        __syncthreads();
        uint32_t base = smb + (uint32_t)((s & 1) * STAGE_B);
#pragma unroll
        for (int p = 0; p < 4; p++) {
            uint32_t abase = base + p * 4096;
            uint32_t bbase = abase + 16384;
            uint32_t brow0 = (uint32_t)(n0w + (lane & 7) + ((lane >> 4) << 3));
            uint32_t bhalf = (uint32_t)((lane >> 3) & 1);
            uint4 bf01 = ldsm_x4(bbase + (((brow0 + p) & 127) * 32) + bhalf * 16);
            uint4 bf23 = ldsm_x4(bbase + (((brow0 + 16 + p) & 127) * 32) + bhalf * 16);
            uint32_t arow = (uint32_t)(m0w + (lane & 15));
            uint32_t ahalf = (uint32_t)(lane >> 4);
            uint4 af[4];
#pragma unroll
            for (int im = 0; im < 4; im++)
                af[im] = ldsm_x4(abase + (((arow + im * 16 + p) & 127) * 32) + ahalf * 16);
#pragma unroll
            for (int im = 0; im < 4; im++) {
                mma16816(acc[im][0], af[im], bf01.x, bf01.y);
                mma16816(acc[im][1], af[im], bf01.z, bf01.w);
                mma16816(acc[im][2], af[im], bf23.x, bf23.y);
                mma16816(acc[im][3], af[im], bf23.z, bf23.w);
            }
        }
        __syncthreads();
        if (s + 2 < NSTAGE_LOGITS) issue_stage(s + 2);
        else asm volatile("cp.async.commit_group;");
    }

    // ---------------- epilogue ----------------
    int gm = lane >> 2, gn = 2 * (lane & 3);
#pragma unroll
    for (int im = 0; im < 4; im++) {
#pragma unroll
        for (int jn = 0; jn < 4; jn++) {
            int col = v0 + n0w + jn * 8 + gn;
            float2 bb = *(const float2*)(b_fc + col);
            int row = i0 + m0w + im * 16 + gm;
            float2 o0 = make_float2(acc[im][jn][0] + bb.x, acc[im][jn][1] + bb.y);
            float2 o1 = make_float2(acc[im][jn][2] + bb.x, acc[im][jn][3] + bb.y);
            __stcs((float2*)(out + (size_t)row * VOCAB + col), o0);
            __stcs((float2*)(out + (size_t)(row + 8) * VOCAB + col), o1);
        }
    }
}

// ================= split kernels (fp32 -> bf16 hi/lo, folded-K layout) =================
__global__ void split_W(const float* __restrict__ W_fc) {
    int idx = blockIdx.x * 256 + threadIdx.x;        // 32000*128
    int v = idx >> 7, q = idx & 127;
    int k = q * 4;
    float4 w = *(const float4*)(W_fc + (size_t)v * HDIM + k);
    __nv_bfloat16 h0 = __float2bfloat16_rn(w.x), h1 = __float2bfloat16_rn(w.y);
    __nv_bfloat16 h2 = __float2bfloat16_rn(w.z), h3 = __float2bfloat16_rn(w.w);
    __nv_bfloat16 l0 = __float2bfloat16_rn(w.x - __bfloat162float(h0));
    __nv_bfloat16 l1 = __float2bfloat16_rn(w.y - __bfloat162float(h1));
    __nv_bfloat16 l2 = __float2bfloat16_rn(w.z - __bfloat162float(h2));
    __nv_bfloat16 l3 = __float2bfloat16_rn(w.w - __bfloat162float(h3));
    ushort4 hv = make_ushort4(__bfloat16_as_ushort(h0), __bfloat16_as_ushort(h1),
                              __bfloat16_as_ushort(h2), __bfloat16_as_ushort(h3));
    ushort4 lv = make_ushort4(__bfloat16_as_ushort(l0), __bfloat16_as_ushort(l1),
                              __bfloat16_as_ushort(l2), __bfloat16_as_ushort(l3));
    __nv_bfloat16* row = g_WX + (size_t)v * KX;
    *(ushort4*)(row + k)        = hv;   // [0,512) = hi
    *(ushort4*)(row + 512 + k)  = lv;   // [512,1024) = lo
    *(ushort4*)(row + 1024 + k) = hv;   // [1024,1536) = hi
}

__global__ void split_H(void) {
    int idx = blockIdx.x * 256 + threadIdx.x;        // 2048*128
    int i = idx >> 7, q = idx & 127;
    int k = q * 4;
    float4 w = *(const float4*)(g_H + (size_t)i * HDIM + k);
    __nv_bfloat16 h0 = __float2bfloat16_rn(w.x), h1 = __float2bfloat16_rn(w.y);
    __nv_bfloat16 h2 = __float2bfloat16_rn(w.z), h3 = __float2bfloat16_rn(w.w);
    __nv_bfloat16 l0 = __float2bfloat16_rn(w.x - __bfloat162float(h0));
    __nv_bfloat16 l1 = __float2bfloat16_rn(w.y - __bfloat162float(h1));
    __nv_bfloat16 l2 = __float2bfloat16_rn(w.z - __bfloat162float(h2));
    __nv_bfloat16 l3 = __float2bfloat16_rn(w.w - __bfloat162float(h3));
    ushort4 hv = make_ushort4(__bfloat16_as_ushort(h0), __bfloat16_as_ushort(h1),
                              __bfloat16_as_ushort(h2), __bfloat16_as_ushort(h3));
    ushort4 lv = make_ushort4(__bfloat16_as_ushort(l0), __bfloat16_as_ushort(l1),
                              __bfloat16_as_ushort(l2), __bfloat16_as_ushort(l3));
    __nv_bfloat16* row = g_HX + (size_t)i * KX;
    *(ushort4*)(row + k)        = hv;   // [0,512) = hi
    *(ushort4*)(row + 512 + k)  = hv;   // [512,1024) = hi (pairs with W_lo)
    *(ushort4*)(row + 1024 + k) = lv;   // [1024,1536) = lo (pairs with W_hi)
}

// ================= FFMA2 GEMM (precompute only): XPt = emb[tok] @ W_ih^T + biases =================
#define KC 16
__global__ void __launch_bounds__(256, 2)
precomp_gemm(const float* __restrict__ Bsrc,
             const float* __restrict__ bias0,
             const float* __restrict__ bias1,
             const int*   __restrict__ tokens,
             const float* __restrict__ emb) {
    __shared__ ull sAu[KC * 65];
    __shared__ ull sBu[KC * 130];
    float* fA = (float*)sAu;

    int tid = threadIdx.x;
    int i0 = blockIdx.x * 128;
    int v0 = blockIdx.y * 128;
    int tm = tid & 15;
    int tv = tid >> 4;

    int mA1 = tid >> 2, k4 = tid & 3;
    int mA2 = mA1 + 64;
    int krow0 = k4 * 4;

    int t1 = tokens[i0 + mA1], t2 = tokens[i0 + mA2];
    const float* pA1 = emb + (size_t)t1 * 512 + k4 * 4;
    const float* pA2 = emb + (size_t)t2 * 512 + k4 * 4;
    const float* pB1 = Bsrc + (size_t)(v0 + mA1) * 512 + k4 * 4;
    const float* pB2 = Bsrc + (size_t)(v0 + mA2) * 512 + k4 * 4;

    int baseA1 = ((mA1 >> 1) & 3) * 32 + (mA1 >> 3) * 2 + (mA1 & 1);
    int baseA2 = ((mA2 >> 1) & 3) * 32 + (mA2 >> 3) * 2 + (mA2 & 1);

    ull acc[4][8];
#pragma unroll
    for (int p = 0; p < 4; p++)
#pragma unroll
        for (int v = 0; v < 8; v++) acc[p][v] = pack2(0.0f, 0.0f);

    float4 ra1 = *(const float4*)pA1;
    float4 ra2 = *(const float4*)pA2;
    float4 rb1 = *(const float4*)pB1;
    float4 rb2 = *(const float4*)pB2;

    for (int c = 0; c < 32; c++) {
        __syncthreads();
        fA[(krow0 + 0) * 130 + baseA1] = ra1.x;
        fA[(krow0 + 1) * 130 + baseA1] = ra1.y;
        fA[(krow0 + 2) * 130 + baseA1] = ra1.z;
        fA[(krow0 + 3) * 130 + baseA1] = ra1.w;
        fA[(krow0 + 0) * 130 + baseA2] = ra2.x;
        fA[(krow0 + 1) * 130 + baseA2] = ra2.y;
        fA[(krow0 + 2) * 130 + baseA2] = ra2.z;
        fA[(krow0 + 3) * 130 + baseA2] = ra2.w;
        sBu[(krow0 + 0) * 130 + mA1] = pack2(rb1.x, rb1.x);
        sBu[(krow0 + 1) * 130 + mA1] = pack2(rb1.y, rb1.y);
        sBu[(krow0 + 2) * 130 + mA1] = pack2(rb1.z, rb1.z);
        sBu[(krow0 + 3) * 130 + mA1] = pack2(rb1.w, rb1.w);
        sBu[(krow0 + 0) * 130 + mA2] = pack2(rb2.x, rb2.x);
        sBu[(krow0 + 1) * 130 + mA2] = pack2(rb2.y, rb2.y);
        sBu[(krow0 + 2) * 130 + mA2] = pack2(rb2.z, rb2.z);
        sBu[(krow0 + 3) * 130 + mA2] = pack2(rb2.w, rb2.w);
        __syncthreads();

        if (c < 31) {
            int off = (c + 1) * KC;
            ra1 = *(const float4*)(pA1 + off);
            ra2 = *(const float4*)(pA2 + off);
            rb1 = *(const float4*)(pB1 + off);
            rb2 = *(const float4*)(pB2 + off);
        }

#pragma unroll
        for (int k = 0; k < KC; k++) {
            ull a[4];
#pragma unroll
            for (int p = 0; p < 4; p++) a[p] = sAu[k * 65 + p * 16 + tm];
            ull bd[8];
#pragma unroll
            for (int v = 0; v < 8; v++) bd[v] = sBu[k * 130 + tv * 8 + v];
#pragma unroll
            for (int p = 0; p < 4; p++)
#pragma unroll
                for (int v = 0; v < 8; v++) ffma2(acc[p][v], a[p], bd[v]);
        }
    }

    int vb = v0 + tv * 8;
    float bias[8];
#pragma unroll
    for (int v = 0; v < 8; v++) bias[v] = bias0[vb + v] + bias1[vb + v];
#pragma unroll
    for (int p = 0; p < 4; p++) {
        int ilo = i0 + tm * 8 + 2 * p;
        int ihi = ilo + 1;
        size_t blo = (size_t)(ilo >> 5) * (G4 * BATCH) + (ilo & 31);
        size_t bhi = (size_t)(ihi >> 5) * (G4 * BATCH) + (ihi & 31);
#pragma unroll
        for (int v = 0; v < 8; v++) {
            float rl, rh; unpack2(acc[p][v], rl, rh);
            size_t goff = (size_t)(vb + v) * 32;
            g_XPt[blo + goff] = rl + bias[v];
            g_XPt[bhi + goff] = rh + bias[v];
        }
    }
}

// ================= one-time W_hh transpose =================
__global__ void prep_W4(const float* __restrict__ W_hh) {
    int idx = blockIdx.x * 256 + threadIdx.x;
    int j = idx >> 9, k = idx & 511;
    g_W4[(size_t)j * 512 + k] = make_float4(
        W_hh[(size_t)(0 * 512 + j) * 512 + k],
        W_hh[(size_t)(1 * 512 + j) * 512 + k],
        W_hh[(size_t)(2 * 512 + j) * 512 + k],
        W_hh[(size_t)(3 * 512 + j) * 512 + k]);
}

// ================= init =================
__global__ void init_kernel(const float* __restrict__ h0, const float* __restrict__ c0) {
    int idx = blockIdx.x * blockDim.x + threadIdx.x;
    if (idx < BATCH * HDIM) {
        int j = idx >> 5, b = idx & 31;
        ((float*)g_hT4[0])[(j >> 2) * 128 + b * 4 + (j & 3)] = h0[b * HDIM + j];
        g_cT[j * 32 + b] = c0[b * HDIM + j];
    }
}

// ================= recurrent step: K-split x8, CTA = one j =================
__global__ void __launch_bounds__(256, 4)
recurrent_kernel(const int* __restrict__ tokens, int t) {
    __shared__ float4 sred[8][32];
    int tid = threadIdx.x;
    int w = tid >> 5, b = tid & 31;
    int j = blockIdx.x;

    const float4*  hT = g_hT4[t & 1];
    const double2* wp = (const double2*)(g_W4 + (size_t)j * 512) + (size_t)w * 64;
    const float4*  hp = hT + w * 16 * 32;

    ull aif0 = pack2(0.0f, 0.0f), aif1 = pack2(0.0f, 0.0f);
    ull ago0 = pack2(0.0f, 0.0f), ago1 = pack2(0.0f, 0.0f);

#pragma unroll
    for (int kk = 0; kk < 16; kk++) {
        float4  h4 = hp[kk * 32 + b];
        double2 w0 = wp[kk * 4 + 0];
        double2 w1 = wp[kk * 4 + 1];
        double2 w2 = wp[kk * 4 + 2];
        double2 w3 = wp[kk * 4 + 3];
        ull hx = pack2(h4.x, h4.x), hy = pack2(h4.y, h4.y);
        ull hz = pack2(h4.z, h4.z), hw = pack2(h4.w, h4.w);
        ffma2(aif0, hx, d2u(w0.x));
        ffma2(ago0, hx, d2u(w0.y));
        ffma2(aif1, hy, d2u(w1.x));
        ffma2(ago1, hy, d2u(w1.y));
        ffma2(aif0, hz, d2u(w2.x));
        ffma2(ago0, hz, d2u(w2.y));
        ffma2(aif1, hw, d2u(w3.x));
        ffma2(ago1, hw, d2u(w3.y));
    }

    float ia, fa, ib, fb, ga, oa, gb, ob;
    unpack2(aif0, ia, fa); unpack2(aif1, ib, fb);
    unpack2(ago0, ga, oa); unpack2(ago1, gb, ob);
    sred[w][b] = make_float4(ia + ib, fa + fb, ga + gb, oa + ob);
    __syncthreads();

    if (w == 0) {
        float4 acc4 = sred[0][b];
#pragma unroll
        for (int q = 1; q < 8; q++) {
            float4 s = sred[q][b];
            acc4.x += s.x; acc4.y += s.y; acc4.z += s.z; acc4.w += s.w;
        }
        size_t xb = (size_t)t * (G4 * BATCH) + (size_t)b;
        float ig = acc4.x + g_XPt[xb + (size_t)(0 * 512 + j) * 32];
        float fg = acc4.y + g_XPt[xb + (size_t)(1 * 512 + j) * 32];
        float gg = acc4.z + g_XPt[xb + (size_t)(2 * 512 + j) * 32];
        float og = acc4.w + g_XPt[xb + (size_t)(3 * 512 + j) * 32];

        float iv = 1.0f / (1.0f + expf(-ig));
        float fv = 1.0f / (1.0f + expf(-fg));
        float gv = tanhf(gg);
        float ov = 1.0f / (1.0f + expf(-og));

        float cold = g_cT[j * 32 + b];
        float ctmp = fv * cold + iv * gv;
        float htmp = ov * tanhf(ctmp);
        bool  msk  = tokens[t * BATCH + b] != 0;   // PAD = 0

        g_H[((size_t)t * BATCH + b) * HDIM + j] = htmp;
        float hold = ((const float*)hT)[(j >> 2) * 128 + b * 4 + (j & 3)];
        ((float*)g_hT4[(t + 1) & 1])[(j >> 2) * 128 + b * 4 + (j & 3)] = msk ? htmp : hold;
        g_cT[j * 32 + b] = msk ? ctmp : cold;
    }
}

// ================= launch =================
extern "C" void kernel_launch(void* const* d_in, const int* in_sizes, int n_in,
                              void* d_out, int out_size) {
    const int*   tokens = (const int*)d_in[0];
    const float* emb    = (const float*)d_in[1];
    const float* W_ih   = (const float*)d_in[2];
    const float* W_hh   = (const float*)d_in[3];
    const float* b_ih   = (const float*)d_in[4];
    const float* b_hh   = (const float*)d_in[5];
    const float* W_fc   = (const float*)d_in[6];
    const float* b_fc   = (const float*)d_in[7];
    const float* h0     = (const float*)d_in[8];
    const float* c0     = (const float*)d_in[9];
    float* out = (float*)d_out;

    cudaFuncSetAttribute(logits_mma, cudaFuncAttributeMaxDynamicSharedMemorySize, 2 * STAGE_B);

    init_kernel<<<64, 256>>>(h0, c0);
    prep_W4<<<1024, 256>>>(W_hh);
    split_W<<<16000, 256>>>(W_fc);

    // XPt = emb[tok] @ W_ih^T + (b_ih + b_hh):  M=2048, N=2048, K=512
    precomp_gemm<<<dim3(16, 16), 256>>>(W_ih, b_ih, b_hh, tokens, emb);

    for (int t = 0; t < T_STEPS; t++)
        recurrent_kernel<<<512, 256>>>(tokens, t);

    split_H<<<1024, 256>>>();

    // out = HX @ WX^T + b_fc:  M=2048, N=32000, K'=1536 (bf16x3 folded)
    logits_mma<<<dim3(16, 250), 256, 2 * STAGE_B>>>(b_fc, out);
}